// round 1
// baseline (speedup 1.0000x reference)
#include <cuda_runtime.h>

// DeformationGrid: trilinear interpolation of a [160,160,160,3] float grid
// at N=4194304 random points in the unit cube.
//
// Layout: grid[x][y][z][c], c fastest. Strides (floats): x: 160*160*3=76800,
// y: 160*3=480, z: 3.
//
// One thread per point. 24 gather loads (8 corners x 3 channels), nested
// fused lerps, 3 stores. Grid (49MB) is fully L2-resident.

#define GRID_R 160

__device__ __forceinline__ float flerp(float a, float b, float t) {
    return fmaf(t, b - a, a);
}

__global__ void __launch_bounds__(256)
trilerp_kernel(const float* __restrict__ coords,
               const float* __restrict__ grid,
               float* __restrict__ out,
               int n)
{
    int i = blockIdx.x * blockDim.x + threadIdx.x;
    if (i >= n) return;

    float cx = coords[3 * i + 0];
    float cy = coords[3 * i + 1];
    float cz = coords[3 * i + 2];

    const float scale = (float)(GRID_R - 1);   // 159
    float px = cx * scale, py = cy * scale, pz = cz * scale;

    float fx0 = floorf(px), fy0 = floorf(py), fz0 = floorf(pz);
    float fx = px - fx0, fy = py - fy0, fz = pz - fz0;

    int ix = (int)fx0, iy = (int)fy0, iz = (int)fz0;
    // Safety clamps. For in-range coords these are no-ops; at the upper
    // boundary the +1 corner has weight 0, so clamping matches cval=0.
    ix = min(max(ix, 0), GRID_R - 1);
    iy = min(max(iy, 0), GRID_R - 1);
    iz = min(max(iz, 0), GRID_R - 1);
    int ix1 = min(ix + 1, GRID_R - 1);
    int iy1 = min(iy + 1, GRID_R - 1);
    int iz1 = min(iz + 1, GRID_R - 1);

    const int SX = GRID_R * GRID_R * 3;  // 76800
    const int SY = GRID_R * 3;           // 480

    int base = ix * SX + iy * SY + iz * 3;
    int dx = (ix1 - ix) * SX;
    int dy = (iy1 - iy) * SY;
    int dz = (iz1 - iz) * 3;

    // 8 corner base offsets
    int a000 = base;
    int a001 = base + dz;
    int a010 = base + dy;
    int a011 = base + dy + dz;
    int a100 = base + dx;
    int a101 = base + dx + dz;
    int a110 = base + dx + dy;
    int a111 = base + dx + dy + dz;

    // Issue all 24 gathers up front for max MLP.
    float v[8][3];
#pragma unroll
    for (int c = 0; c < 3; c++) {
        v[0][c] = __ldg(grid + a000 + c);
        v[1][c] = __ldg(grid + a001 + c);
        v[2][c] = __ldg(grid + a010 + c);
        v[3][c] = __ldg(grid + a011 + c);
        v[4][c] = __ldg(grid + a100 + c);
        v[5][c] = __ldg(grid + a101 + c);
        v[6][c] = __ldg(grid + a110 + c);
        v[7][c] = __ldg(grid + a111 + c);
    }

    float res[3];
#pragma unroll
    for (int c = 0; c < 3; c++) {
        float c00 = flerp(v[0][c], v[1][c], fz);
        float c01 = flerp(v[2][c], v[3][c], fz);
        float c10 = flerp(v[4][c], v[5][c], fz);
        float c11 = flerp(v[6][c], v[7][c], fz);
        float c0  = flerp(c00, c01, fy);
        float c1  = flerp(c10, c11, fy);
        res[c] = flerp(c0, c1, fx);
    }

    out[3 * i + 0] = res[0];
    out[3 * i + 1] = res[1];
    out[3 * i + 2] = res[2];
}

extern "C" void kernel_launch(void* const* d_in, const int* in_sizes, int n_in,
                              void* d_out, int out_size) {
    const float* coords = (const float*)d_in[0];   // [N,3]
    const float* theta  = (const float*)d_in[1];   // [160,160,160,3]
    float* out = (float*)d_out;                    // [N,3]
    int n = in_sizes[0] / 3;
    int threads = 256;
    int blocks = (n + threads - 1) / threads;
    trilerp_kernel<<<blocks, threads>>>(coords, theta, out, n);
}

// round 3
// speedup vs baseline: 1.1289x; 1.1289x over previous
#include <cuda_runtime.h>

// DeformationGrid: trilinear interpolation of a [160,160,160,3] float grid
// at N=4194304 random points in the unit cube.
//
// R2 strategy: repack theta into a float4-padded grid (16B/voxel) held in a
// __device__ scratch array so each of the 8 corner gathers is a single
// LDG.128 instead of three LDG.32. This cuts L1tex wavefront work ~3x
// (the R1 bottleneck at 68.6%). The 65.5MB padded grid stays L2-resident.

#define GRID_R 160
#define NVOX (GRID_R * GRID_R * GRID_R)   // 4,096,000

// Scratch: padded grid, 16 bytes per voxel. (.bss device global — allowed.)
__device__ float4 g_grid4[NVOX];

// ---------------------------------------------------------------------------
// Repack: [160^3, 3] floats -> [160^3] float4 (w = 0).
// Each thread handles 4 voxels = 12 input floats (3x float4 in, 4x float4 out).
// ---------------------------------------------------------------------------
__global__ void __launch_bounds__(256)
repack_kernel(const float* __restrict__ theta)
{
    int i = blockIdx.x * blockDim.x + threadIdx.x;     // group of 4 voxels
    if (i >= NVOX / 4) return;
    const float4* t4 = (const float4*)theta;
    float4 a = __ldg(t4 + 3 * i + 0);
    float4 b = __ldg(t4 + 3 * i + 1);
    float4 c = __ldg(t4 + 3 * i + 2);
    float4* o = g_grid4 + 4 * i;
    o[0] = make_float4(a.x, a.y, a.z, 0.0f);
    o[1] = make_float4(a.w, b.x, b.y, 0.0f);
    o[2] = make_float4(b.z, b.w, c.x, 0.0f);
    o[3] = make_float4(c.y, c.z, c.w, 0.0f);
}

// ---------------------------------------------------------------------------
// Gather: one thread per point, 8 float4 corner loads, fused lerps.
// ---------------------------------------------------------------------------
__device__ __forceinline__ float flerp(float a, float b, float t) {
    return fmaf(t, b - a, a);
}

__global__ void __launch_bounds__(256)
trilerp_kernel(const float* __restrict__ coords,
               float* __restrict__ out,
               int n)
{
    int i = blockIdx.x * blockDim.x + threadIdx.x;
    if (i >= n) return;

    float cx = coords[3 * i + 0];
    float cy = coords[3 * i + 1];
    float cz = coords[3 * i + 2];

    const float scale = (float)(GRID_R - 1);   // 159
    float px = cx * scale, py = cy * scale, pz = cz * scale;

    float fx0 = floorf(px), fy0 = floorf(py), fz0 = floorf(pz);
    float fx = px - fx0, fy = py - fy0, fz = pz - fz0;

    int ix = (int)fx0, iy = (int)fy0, iz = (int)fz0;
    // Safety clamps. For in-range coords these are no-ops; at the upper
    // boundary the +1 corner has weight 0, so clamping matches cval=0.
    ix = min(max(ix, 0), GRID_R - 1);
    iy = min(max(iy, 0), GRID_R - 1);
    iz = min(max(iz, 0), GRID_R - 1);
    int ix1 = min(ix + 1, GRID_R - 1);
    int iy1 = min(iy + 1, GRID_R - 1);
    int iz1 = min(iz + 1, GRID_R - 1);

    const int SX = GRID_R * GRID_R;  // voxel strides in the float4 grid
    const int SY = GRID_R;

    int base = ix * SX + iy * SY + iz;
    int dx = (ix1 - ix) * SX;
    int dy = (iy1 - iy) * SY;
    int dz = (iz1 - iz);

    const float4* g = g_grid4;
    float4 v000 = __ldg(g + base);
    float4 v001 = __ldg(g + base + dz);
    float4 v010 = __ldg(g + base + dy);
    float4 v011 = __ldg(g + base + dy + dz);
    float4 v100 = __ldg(g + base + dx);
    float4 v101 = __ldg(g + base + dx + dz);
    float4 v110 = __ldg(g + base + dx + dy);
    float4 v111 = __ldg(g + base + dx + dy + dz);

    // lerp along z
    float c00x = flerp(v000.x, v001.x, fz), c00y = flerp(v000.y, v001.y, fz), c00z = flerp(v000.z, v001.z, fz);
    float c01x = flerp(v010.x, v011.x, fz), c01y = flerp(v010.y, v011.y, fz), c01z = flerp(v010.z, v011.z, fz);
    float c10x = flerp(v100.x, v101.x, fz), c10y = flerp(v100.y, v101.y, fz), c10z = flerp(v100.z, v101.z, fz);
    float c11x = flerp(v110.x, v111.x, fz), c11y = flerp(v110.y, v111.y, fz), c11z = flerp(v110.z, v111.z, fz);
    // lerp along y
    float c0x = flerp(c00x, c01x, fy), c0y = flerp(c00y, c01y, fy), c0z = flerp(c00z, c01z, fy);
    float c1x = flerp(c10x, c11x, fy), c1y = flerp(c10y, c11y, fy), c1z = flerp(c10z, c11z, fy);
    // lerp along x
    out[3 * i + 0] = flerp(c0x, c1x, fx);
    out[3 * i + 1] = flerp(c0y, c1y, fx);
    out[3 * i + 2] = flerp(c0z, c1z, fx);
}

extern "C" void kernel_launch(void* const* d_in, const int* in_sizes, int n_in,
                              void* d_out, int out_size) {
    const float* coords = (const float*)d_in[0];   // [N,3]
    const float* theta  = (const float*)d_in[1];   // [160,160,160,3]
    float* out = (float*)d_out;                    // [N,3]
    int n = in_sizes[0] / 3;

    int rt = 256;
    int rgroups = NVOX / 4;
    repack_kernel<<<(rgroups + rt - 1) / rt, rt>>>(theta);

    int threads = 256;
    int blocks = (n + threads - 1) / threads;
    trilerp_kernel<<<blocks, threads>>>(coords, out, n);
}

// round 5
// speedup vs baseline: 1.5950x; 1.4128x over previous
#include <cuda_runtime.h>
#include <cuda_fp16.h>

// DeformationGrid: trilinear interpolation of a [160,160,160,3] float grid
// at N=4194304 random points in the unit cube.
//
// R4 = R3 with the compile fix (raw reinterpret instead of the nonexistent
// __half2_as_ushort2 intrinsics).
//
// Strategy: the two z-corners of every lookup are adjacent in z. Repack
// theta into z-pair entries: entry[x][y][z] = {v[x,y,z], v[x,y,z+1]} stored
// as 6 halves + 2 pad halves = 16B. Each point then needs only 4 LDG.128
// (one per (x,y) corner combo) instead of 8 — halving L1tex wavefront work
// (the R2 bottleneck at 85.9%) and halving L2 sector traffic. Footprint
// stays 65.5MB (L2-resident). Arithmetic is fp32; half storage adds ~3e-4
// relative error, well under the 1e-3 gate.

#define GRID_R 160
#define NVOX (GRID_R * GRID_R * GRID_R)   // 4,096,000

// 16B z-pair entry: halves [c0z0,c1z0,c2z0, c0z1,c1z1,c2z1, pad,pad]
__device__ uint4 g_pair[NVOX];            // 65.5 MB scratch (.bss — allowed)

__device__ __forceinline__ unsigned h2_to_u32(__half2 h) {
    return *reinterpret_cast<unsigned*>(&h);
}
__device__ __forceinline__ __half2 u32_to_h2(unsigned u) {
    return *reinterpret_cast<__half2*>(&u);
}

// ---------------------------------------------------------------------------
// Repack: one block per (x,y) row of 160 z-voxels.
// Coalesced: reads 480 contiguous floats into smem, writes 160 x 16B entries.
// ---------------------------------------------------------------------------
__global__ void __launch_bounds__(160)
repack_kernel(const float* __restrict__ theta)
{
    __shared__ float s[480];
    int row = blockIdx.x;                  // x*160 + y, 0..25599
    int t = threadIdx.x;                   // 0..159
    const float* src = theta + (size_t)row * 480;
    s[t]       = __ldg(src + t);
    s[t + 160] = __ldg(src + t + 160);
    s[t + 320] = __ldg(src + t + 320);
    __syncthreads();

    int z1 = min(t + 1, GRID_R - 1);       // z=159 entry duplicates (weight-0)
    uint4 e;
    e.x = h2_to_u32(__floats2half2_rn(s[3 * t + 0], s[3 * t + 1]));
    e.y = h2_to_u32(__floats2half2_rn(s[3 * t + 2], s[3 * z1 + 0]));
    e.z = h2_to_u32(__floats2half2_rn(s[3 * z1 + 1], s[3 * z1 + 2]));
    e.w = 0u;
    g_pair[(size_t)row * GRID_R + t] = e;
}

// ---------------------------------------------------------------------------
// Gather: one thread per point, 4 LDG.128 corner-pair loads, fused lerps.
// ---------------------------------------------------------------------------
__device__ __forceinline__ float flerp(float a, float b, float t) {
    return fmaf(t, b - a, a);
}

// Decode entry -> z-lerped channel triple (fp32).
__device__ __forceinline__ void zlerp_entry(uint4 e, float fz,
                                            float& r0, float& r1, float& r2)
{
    float2 p0 = __half22float2(u32_to_h2(e.x));   // (c0z0, c1z0)
    float2 p1 = __half22float2(u32_to_h2(e.y));   // (c2z0, c0z1)
    float2 p2 = __half22float2(u32_to_h2(e.z));   // (c1z1, c2z1)
    r0 = flerp(p0.x, p1.y, fz);
    r1 = flerp(p0.y, p2.x, fz);
    r2 = flerp(p1.x, p2.y, fz);
}

__global__ void __launch_bounds__(256)
trilerp_kernel(const float* __restrict__ coords,
               float* __restrict__ out,
               int n)
{
    int i = blockIdx.x * blockDim.x + threadIdx.x;
    if (i >= n) return;

    float cx = coords[3 * i + 0];
    float cy = coords[3 * i + 1];
    float cz = coords[3 * i + 2];

    const float scale = (float)(GRID_R - 1);   // 159
    float px = cx * scale, py = cy * scale, pz = cz * scale;

    float fx0 = floorf(px), fy0 = floorf(py), fz0 = floorf(pz);
    float fx = px - fx0, fy = py - fy0, fz = pz - fz0;

    int ix = (int)fx0, iy = (int)fy0, iz = (int)fz0;
    // Safety clamps. In-range coords: no-ops. Upper boundary: the +1 corner
    // has weight 0, so replicate-clamp matches cval=0 semantics.
    ix = min(max(ix, 0), GRID_R - 1);
    iy = min(max(iy, 0), GRID_R - 1);
    iz = min(max(iz, 0), GRID_R - 1);
    int ix1 = min(ix + 1, GRID_R - 1);
    int iy1 = min(iy + 1, GRID_R - 1);

    const int SX = GRID_R * GRID_R;
    const int SY = GRID_R;

    int b00 = ix  * SX + iy  * SY + iz;
    int b01 = ix  * SX + iy1 * SY + iz;
    int b10 = ix1 * SX + iy  * SY + iz;
    int b11 = ix1 * SX + iy1 * SY + iz;

    // 4 gathers, each returns both z-corners for one (x,y) combo.
    uint4 e00 = __ldg(g_pair + b00);
    uint4 e01 = __ldg(g_pair + b01);
    uint4 e10 = __ldg(g_pair + b10);
    uint4 e11 = __ldg(g_pair + b11);

    float c00x, c00y, c00z, c01x, c01y, c01z;
    float c10x, c10y, c10z, c11x, c11y, c11z;
    zlerp_entry(e00, fz, c00x, c00y, c00z);
    zlerp_entry(e01, fz, c01x, c01y, c01z);
    zlerp_entry(e10, fz, c10x, c10y, c10z);
    zlerp_entry(e11, fz, c11x, c11y, c11z);

    // lerp along y
    float c0x = flerp(c00x, c01x, fy), c0y = flerp(c00y, c01y, fy), c0z = flerp(c00z, c01z, fy);
    float c1x = flerp(c10x, c11x, fy), c1y = flerp(c10y, c11y, fy), c1z = flerp(c10z, c11z, fy);
    // lerp along x
    out[3 * i + 0] = flerp(c0x, c1x, fx);
    out[3 * i + 1] = flerp(c0y, c1y, fx);
    out[3 * i + 2] = flerp(c0z, c1z, fx);
}

extern "C" void kernel_launch(void* const* d_in, const int* in_sizes, int n_in,
                              void* d_out, int out_size) {
    const float* coords = (const float*)d_in[0];   // [N,3]
    const float* theta  = (const float*)d_in[1];   // [160,160,160,3]
    float* out = (float*)d_out;                    // [N,3]
    int n = in_sizes[0] / 3;

    repack_kernel<<<GRID_R * GRID_R, GRID_R>>>(theta);

    int threads = 256;
    int blocks = (n + threads - 1) / threads;
    trilerp_kernel<<<blocks, threads>>>(coords, out, n);
}